// round 5
// baseline (speedup 1.0000x reference)
#include <cuda_runtime.h>

#define BB 8
#define NN 16384
#define DD 512
#define MV 8
#define SS 128                      // N-splits in pass 1
#define RPS (NN / SS)               // rows per split = 128
#define NBLK 128                    // blocks per batch in pass 3
#define SCALE_F 0.1f
#define EPS_F 1e-5f

__device__ float g_partial[BB][SS][DD];   // 2 MB  column partial sums
__device__ float g_SW2[BB][MV][DD];       // SCALE * Cayley-folded Wo (fp32)
__device__ float g_F[BB][DD];             // SCALE * (bo + sum_i bp_i*W2_i)

// ---- packed f32x2 helpers (sm_103a FFMA2 path) ------------------------------
union U2 { float4 f; float s[4]; unsigned long long u[2]; };

__device__ __forceinline__ unsigned long long splat2(float x) {
    unsigned long long r;
    asm("mov.b64 %0, {%1, %1};" : "=l"(r) : "f"(x));
    return r;
}
__device__ __forceinline__ void fmaacc2(unsigned long long& d,
                                        unsigned long long a, unsigned long long b) {
    asm("fma.rn.f32x2 %0, %1, %2, %0;" : "+l"(d) : "l"(a), "l"(b));
}
__device__ __forceinline__ unsigned long long fma2(unsigned long long a,
                                                   unsigned long long b,
                                                   unsigned long long c) {
    unsigned long long d;
    asm("fma.rn.f32x2 %0, %1, %2, %3;" : "=l"(d) : "l"(a), "l"(b), "l"(c));
    return d;
}
__device__ __forceinline__ void addacc2(unsigned long long& d, unsigned long long a) {
    asm("add.rn.f32x2 %0, %1, %0;" : "+l"(d) : "l"(a));
}
__device__ __forceinline__ float2 unpack2(unsigned long long v) {
    float2 r;
    asm("mov.b64 {%0, %1}, %2;" : "=f"(r.x), "=f"(r.y) : "l"(v));
    return r;
}

// ---------------------------------------------------------------------------
// Pass 1: pure streaming column sums (proven ~44us @ 79% DRAM).
// ---------------------------------------------------------------------------
__global__ void k_partial(const float* __restrict__ x) {
    int b = blockIdx.y, s = blockIdx.x, t = threadIdx.x;  // t in [0,128)
    const float4* xp = (const float4*)(x + ((size_t)b * NN + (size_t)s * RPS) * DD);
    float4 a0 = make_float4(0.f, 0.f, 0.f, 0.f);
    float4 a1 = make_float4(0.f, 0.f, 0.f, 0.f);
#pragma unroll 4
    for (int r = 0; r < RPS; r += 2) {
        float4 v0 = xp[(size_t)r * 128 + t];
        float4 v1 = xp[(size_t)(r + 1) * 128 + t];
        a0.x += v0.x; a0.y += v0.y; a0.z += v0.z; a0.w += v0.w;
        a1.x += v1.x; a1.y += v1.y; a1.z += v1.z; a1.w += v1.w;
    }
    a0.x += a1.x; a0.y += a1.y; a0.z += a1.z; a0.w += a1.w;
    ((float4*)&g_partial[b][s][0])[t] = a0;
}

// ---------------------------------------------------------------------------
// Pass 2: per-batch prep. mean -> mf -> Cayley fold -> SW2 (fp32), F
// ---------------------------------------------------------------------------
__global__ void k_prep(const float* __restrict__ Wm, const float* __restrict__ bm,
                       const float* __restrict__ Wo, const float* __restrict__ bp,
                       const float* __restrict__ bo) {
    __shared__ float mean_s[DD];
    __shared__ float mf_s[MV];
    __shared__ float M_s[MV][MV];
    int b = blockIdx.x, t = threadIdx.x;  // 512 threads

    float acc = 0.f;
    for (int s = 0; s < SS; ++s) acc += g_partial[b][s][t];
    mean_s[t] = acc * (1.0f / NN);
    __syncthreads();

    int w = t >> 5, l = t & 31;
    if (w < MV) {
        float p = 0.f;
#pragma unroll
        for (int c = 0; c < 16; ++c) p += mean_s[l + 32 * c] * Wm[w * DD + l + 32 * c];
#pragma unroll
        for (int o = 16; o; o >>= 1) p += __shfl_xor_sync(0xffffffffu, p, o);
        if (l == 0) mf_s[w] = p + bm[w];
    }
    __syncthreads();

    if (t < 64) {
        const int maskT[8] = {0, 1, 2, 4, 3, 5, 6, 7};
        const int idxT[8]  = {0, 1, 2, 4, 3, 5, 6, 7};
        int i = t >> 3, j = t & 7;
        int a = maskT[i], bj = maskT[j];
        int sgn = 0, aa = a >> 1;
        while (aa) { sgn += __popc(aa & bj); aa >>= 1; }
        int k = idxT[a ^ bj];
        M_s[i][k] = ((sgn & 1) ? -1.f : 1.f) * mf_s[j];
    }
    __syncthreads();

    float wo[8];
#pragma unroll
    for (int k = 0; k < 8; ++k) wo[k] = Wo[t * 8 + k];
    float fb = 0.f;
#pragma unroll
    for (int i = 0; i < MV; ++i) {
        float w2 = 0.f;
#pragma unroll
        for (int k = 0; k < 8; ++k) w2 += M_s[i][k] * wo[k];
        g_SW2[b][i][t] = SCALE_F * w2;
        fb += bp[i] * w2;
    }
    g_F[b][t] = SCALE_F * (fb + bo[t]);
}

// ---------------------------------------------------------------------------
// Pass 3: fused dots + combine + LN, packed f32x2 math.
// grid (NBLK, BB), 256 threads (8 warps). Warp: 16 rows, 2 per iteration.
// ---------------------------------------------------------------------------
__global__ void __launch_bounds__(256, 2)
k_main(const float* __restrict__ x, const float* __restrict__ Wp,
       const float* __restrict__ gamma, const float* __restrict__ beta,
       float* __restrict__ y) {
    __shared__ float Wp_s[MV * DD];          // 16 KB
    __shared__ float SW2_s[MV * DD];         // 16 KB
    __shared__ float F_s[DD], gm_s[DD], bt_s[DD];
    __shared__ float prbuf[2][8][16];        // ping-pong per-warp dot results

    int b = blockIdx.y, t = threadIdx.x;
    const float* sw2g = &g_SW2[b][0][0];
    for (int i = t; i < MV * DD; i += 256) { Wp_s[i] = Wp[i]; SW2_s[i] = sw2g[i]; }
    for (int i = t; i < DD; i += 256) { F_s[i] = g_F[b][i]; gm_s[i] = gamma[i]; bt_s[i] = beta[i]; }
    __syncthreads();

    int w = t >> 5, l = t & 31;
    int g = l & 7;
    size_t rowbase = (size_t)blockIdx.x * 128 + (size_t)w * 16;
    const float4* xp = (const float4*)(x + ((size_t)b * NN + rowbase) * DD);
    float4* yp = (float4*)(y + ((size_t)b * NN + rowbase) * DD);

    for (int it = 0; it < 8; ++it) {
        int pp = it & 1;
        U2 v0[4], v1[4];
#pragma unroll
        for (int c = 0; c < 4; ++c) {
            v0[c].f = xp[(size_t)(it * 2) * 128 + c * 32 + l];
            v1[c].f = xp[(size_t)(it * 2 + 1) * 128 + c * 32 + l];
        }

        // 8 per-lane partial dots per row (packed f32x2)
        float p0[8], p1[8];
#pragma unroll
        for (int i = 0; i < MV; ++i) {
            unsigned long long a0 = 0ULL, a1 = 0ULL;
#pragma unroll
            for (int c = 0; c < 4; ++c) {
                U2 wv; wv.f = *(const float4*)&Wp_s[i * DD + c * 128 + l * 4];
                fmaacc2(a0, v0[c].u[0], wv.u[0]);
                fmaacc2(a0, v0[c].u[1], wv.u[1]);
                fmaacc2(a1, v1[c].u[0], wv.u[0]);
                fmaacc2(a1, v1[c].u[1], wv.u[1]);
            }
            float2 t0 = unpack2(a0), t1 = unpack2(a1);
            p0[i] = t0.x + t0.y; p1[i] = t1.x + t1.y;
        }
        // group reduce (1,2,4) on 16 values
#pragma unroll
        for (int o = 1; o <= 4; o <<= 1) {
#pragma unroll
            for (int i = 0; i < MV; ++i) {
                p0[i] += __shfl_xor_sync(0xffffffffu, p0[i], o);
                p1[i] += __shfl_xor_sync(0xffffffffu, p1[i], o);
            }
        }
        // lane selects component (l&7), cross-group reduce (8,16)
        float vd0 = p0[0], vd1 = p1[0];
#pragma unroll
        for (int i = 1; i < MV; ++i) { if (g == i) { vd0 = p0[i]; vd1 = p1[i]; } }
        vd0 += __shfl_xor_sync(0xffffffffu, vd0, 8);
        vd0 += __shfl_xor_sync(0xffffffffu, vd0, 16);
        vd1 += __shfl_xor_sync(0xffffffffu, vd1, 8);
        vd1 += __shfl_xor_sync(0xffffffffu, vd1, 16);

        // broadcast via per-warp smem (ping-pong, no extra sync needed)
        if (l < 16) prbuf[pp][w][l] = (l < 8) ? vd0 : vd1;
        __syncwarp();
        U2 q0a, q0b, q1a, q1b;
        q0a.f = *(const float4*)&prbuf[pp][w][0];
        q0b.f = *(const float4*)&prbuf[pp][w][4];
        q1a.f = *(const float4*)&prbuf[pp][w][8];
        q1b.f = *(const float4*)&prbuf[pp][w][12];
        float pr0[8] = {q0a.s[0], q0a.s[1], q0a.s[2], q0a.s[3],
                        q0b.s[0], q0b.s[1], q0b.s[2], q0b.s[3]};
        float pr1[8] = {q1a.s[0], q1a.s[1], q1a.s[2], q1a.s[3],
                        q1b.s[0], q1b.s[1], q1b.s[2], q1b.s[3]};

        // v = x + F + sum_i pr_i * SW2[i][:]   (all packed)
#pragma unroll
        for (int c = 0; c < 4; ++c) {
            U2 f4; f4.f = *(const float4*)&F_s[c * 128 + l * 4];
            addacc2(v0[c].u[0], f4.u[0]); addacc2(v0[c].u[1], f4.u[1]);
            addacc2(v1[c].u[0], f4.u[0]); addacc2(v1[c].u[1], f4.u[1]);
        }
#pragma unroll
        for (int i = 0; i < MV; ++i) {
            unsigned long long s0 = splat2(pr0[i]);
            unsigned long long s1 = splat2(pr1[i]);
#pragma unroll
            for (int c = 0; c < 4; ++c) {
                U2 wv; wv.f = *(const float4*)&SW2_s[i * DD + c * 128 + l * 4];
                fmaacc2(v0[c].u[0], s0, wv.u[0]);
                fmaacc2(v0[c].u[1], s0, wv.u[1]);
                fmaacc2(v1[c].u[0], s1, wv.u[0]);
                fmaacc2(v1[c].u[1], s1, wv.u[1]);
            }
        }

        // LayerNorm stats, packed accumulate
        unsigned long long sa = 0ULL, qa = 0ULL, sb = 0ULL, qb = 0ULL;
#pragma unroll
        for (int c = 0; c < 4; ++c) {
            addacc2(sa, v0[c].u[0]); addacc2(sa, v0[c].u[1]);
            fmaacc2(qa, v0[c].u[0], v0[c].u[0]); fmaacc2(qa, v0[c].u[1], v0[c].u[1]);
            addacc2(sb, v1[c].u[0]); addacc2(sb, v1[c].u[1]);
            fmaacc2(qb, v1[c].u[0], v1[c].u[0]); fmaacc2(qb, v1[c].u[1], v1[c].u[1]);
        }
        float2 tsa = unpack2(sa), tqa = unpack2(qa);
        float2 tsb = unpack2(sb), tqb = unpack2(qb);
        float s0v = tsa.x + tsa.y, q0v = tqa.x + tqa.y;
        float s1v = tsb.x + tsb.y, q1v = tqb.x + tqb.y;
#pragma unroll
        for (int o = 1; o <= 2; o <<= 1) {
            s0v += __shfl_xor_sync(0xffffffffu, s0v, o);
            q0v += __shfl_xor_sync(0xffffffffu, q0v, o);
            s1v += __shfl_xor_sync(0xffffffffu, s1v, o);
            q1v += __shfl_xor_sync(0xffffffffu, q1v, o);
        }
        int g4i = l & 3;
        float sel = s0v;
        if (g4i == 1) sel = q0v;
        if (g4i == 2) sel = s1v;
        if (g4i == 3) sel = q1v;
        sel += __shfl_xor_sync(0xffffffffu, sel, 4);
        sel += __shfl_xor_sync(0xffffffffu, sel, 8);
        sel += __shfl_xor_sync(0xffffffffu, sel, 16);
        float S0 = __shfl_sync(0xffffffffu, sel, 0);
        float Q0 = __shfl_sync(0xffffffffu, sel, 1);
        float S1 = __shfl_sync(0xffffffffu, sel, 2);
        float Q1 = __shfl_sync(0xffffffffu, sel, 3);

        float mu0 = S0 * (1.f / DD), mu1 = S1 * (1.f / DD);
        float r0 = rsqrtf(Q0 * (1.f / DD) - mu0 * mu0 + EPS_F);
        float r1 = rsqrtf(Q1 * (1.f / DD) - mu1 * mu1 + EPS_F);
        unsigned long long rp0 = splat2(r0), mr0 = splat2(-mu0 * r0);
        unsigned long long rp1 = splat2(r1), mr1 = splat2(-mu1 * r1);

#pragma unroll
        for (int c = 0; c < 4; ++c) {
            U2 g4, b4;
            g4.f = *(const float4*)&gm_s[c * 128 + l * 4];
            b4.f = *(const float4*)&bt_s[c * 128 + l * 4];
            U2 o0, o1;
            // e = v*r - mu*r ; o = gamma*e + beta
            o0.u[0] = fma2(g4.u[0], fma2(v0[c].u[0], rp0, mr0), b4.u[0]);
            o0.u[1] = fma2(g4.u[1], fma2(v0[c].u[1], rp0, mr0), b4.u[1]);
            o1.u[0] = fma2(g4.u[0], fma2(v1[c].u[0], rp1, mr1), b4.u[0]);
            o1.u[1] = fma2(g4.u[1], fma2(v1[c].u[1], rp1, mr1), b4.u[1]);
            yp[(size_t)(it * 2) * 128 + c * 32 + l] = o0.f;
            yp[(size_t)(it * 2 + 1) * 128 + c * 32 + l] = o1.f;
        }
    }
}

// ---------------------------------------------------------------------------
extern "C" void kernel_launch(void* const* d_in, const int* in_sizes, int n_in,
                              void* d_out, int out_size) {
    const float* x     = (const float*)d_in[0];
    const float* Wp    = (const float*)d_in[1];
    const float* bp    = (const float*)d_in[2];
    const float* Wm    = (const float*)d_in[3];
    const float* bm    = (const float*)d_in[4];
    const float* Wo    = (const float*)d_in[5];
    const float* bo    = (const float*)d_in[6];
    const float* gamma = (const float*)d_in[7];
    const float* beta  = (const float*)d_in[8];
    float* y = (float*)d_out;

    dim3 g1(SS, BB);
    k_partial<<<g1, 128>>>(x);
    k_prep<<<BB, 512>>>(Wm, bm, Wo, bp, bo);
    dim3 g3(NBLK, BB);
    k_main<<<g3, 256>>>(x, Wp, gamma, beta, y);
}